// round 1
// baseline (speedup 1.0000x reference)
#include <cuda_runtime.h>
#include <cuda_bf16.h>

// Problem shapes (fixed by the dataset): B=1, C=32, H=128, W=256.
// Output: [1, 2C, H, W] float32.
//   channels [0, C):  softargmax over a d-constant cost  -> uniform softmax
//                     -> constant 0.5*(dmin + dmax - 1)
//   channels [C, 2C): softargmax over cost[d] = feaR[c', h, w-d] (valid)
//                     or 0 (invalid -> exp = 1, folded analytically)

#define C_CH 32
#define H_DIM 128
#define W_DIM 256

__global__ void gcnet_softargmax_kernel(const float* __restrict__ feaR,
                                        const int* __restrict__ p_min_disp,
                                        const int* __restrict__ p_max_disp,
                                        float* __restrict__ out) {
    const int h = blockIdx.x;      // 0..H-1
    const int c = blockIdx.y;      // 0..2C-1
    const int w = threadIdx.x;     // 0..W-1

    const int dmin = p_min_disp[0] / 2;   // features are half-res
    const int dmax = p_max_disp[0] / 2;
    const int D = dmax - dmin;

    if (c < C_CH) {
        // Left channels: cost independent of d -> uniform softmax -> mean disparity.
        out[(c * H_DIM + h) * W_DIM + w] = 0.5f * (float)(dmin + dmax - 1);
        return;
    }

    __shared__ float e[W_DIM];
    const int cr = c - C_CH;
    const float x = feaR[(cr * H_DIM + h) * W_DIM + w];
    e[w] = __expf(x);
    __syncthreads();

    // Valid disparity range for this w: 0 <= w - d < W  ->  d in [w-W+1, w]
    int dlo = dmin > (w - W_DIM + 1) ? dmin : (w - W_DIM + 1);
    int dhi = (dmax - 1) < w ? (dmax - 1) : w;
    int nvalid = dhi - dlo + 1;
    if (nvalid < 0) nvalid = 0;

    // Invalid disparities contribute exp(0)=1 each: closed-form sums.
    const float S_total = 0.5f * (float)(dmin + dmax - 1) * (float)D;
    const float S_valid = (nvalid > 0) ? 0.5f * (float)(dlo + dhi) * (float)nvalid : 0.0f;

    float den = (float)(D - nvalid);      // sum of exp(0) over invalid d
    float num = S_total - S_valid;        // sum of d * exp(0) over invalid d

    int j = w - dlo;                      // source column, decreasing
    float df = (float)dlo;                // disparity value, increasing
    #pragma unroll 8
    for (int i = 0; i < nvalid; ++i) {
        const float v = e[j];
        den += v;
        num = fmaf(df, v, num);
        --j;
        df += 1.0f;
    }

    out[(c * H_DIM + h) * W_DIM + w] = num / den;
}

extern "C" void kernel_launch(void* const* d_in, const int* in_sizes, int n_in,
                              void* d_out, int out_size) {
    // metadata order: feaL (unused), feaR, min_disp, max_disp
    const float* feaR = (const float*)d_in[1];
    const int* p_min  = (const int*)d_in[2];
    const int* p_max  = (const int*)d_in[3];
    float* out = (float*)d_out;

    dim3 grid(H_DIM, 2 * C_CH);   // 128 x 64 blocks
    gcnet_softargmax_kernel<<<grid, W_DIM>>>(feaR, p_min, p_max, out);
}

// round 4
// speedup vs baseline: 1.8605x; 1.8605x over previous
#include <cuda_runtime.h>
#include <cuda_bf16.h>

// B=1, C=32, H=128, W=256, D = (max_disp-min_disp)/2 = 64.
// Output [1, 2C, H, W] fp32:
//   ch [0,C):  softargmax of d-constant cost -> uniform -> 0.5*(dmin+dmax-1)
//   ch [C,2C): windowed softargmax of e[j]=exp(feaR[c,h,j]) over j=w-d,
//              computed O(1)/thread via per-row prefix sums P, Q.

#define C_CH 32
#define H_DIM 128
#define W_DIM 256
#define FULLM 0xFFFFFFFFu

__global__ void gcnet_scan_kernel(const float* __restrict__ feaR,
                                  const int* __restrict__ p_min,
                                  const int* __restrict__ p_max,
                                  float* __restrict__ out) {
    const int h    = blockIdx.x;      // 0..H-1
    const int cr   = blockIdx.y;      // 0..C-1 (right-feature channel)
    const int w    = threadIdx.x;     // 0..W-1
    const int lane = w & 31;
    const int warp = w >> 5;

    const int dmin = p_min[0] / 2;    // features are half-res
    const int dmax = p_max[0] / 2;
    const int D    = dmax - dmin;
    const float mean_d = 0.5f * (float)(dmin + dmax - 1);

    // Left channel: cost independent of d -> uniform softmax -> mean disparity.
    out[(cr * H_DIM + h) * W_DIM + w] = mean_d;

    __shared__ float sP[W_DIM + 1];   // exclusive prefix of e[k]
    __shared__ float sQ[W_DIM + 1];   // exclusive prefix of k*e[k]
    __shared__ float wsumP[8];
    __shared__ float wsumQ[8];

    const float x = feaR[(cr * H_DIM + h) * W_DIM + w];
    float p = __expf(x);
    float q = (float)w * p;

    // Warp-level inclusive scan of (p, q).
    #pragma unroll
    for (int off = 1; off < 32; off <<= 1) {
        float tp = __shfl_up_sync(FULLM, p, off);
        float tq = __shfl_up_sync(FULLM, q, off);
        if (lane >= off) { p += tp; q += tq; }
    }
    if (lane == 31) { wsumP[warp] = p; wsumQ[warp] = q; }
    __syncthreads();

    // Cross-warp offset: sum of preceding warp totals (broadcast LDS, cheap).
    float offP = 0.0f, offQ = 0.0f;
    #pragma unroll
    for (int i = 0; i < 7; ++i) {
        if (i < warp) { offP += wsumP[i]; offQ += wsumQ[i]; }
    }
    sP[w + 1] = p + offP;
    sQ[w + 1] = q + offQ;
    if (w == 0) { sP[0] = 0.0f; sQ[0] = 0.0f; }
    __syncthreads();

    // Valid disparity window for this w: d in [dlo, dhi], source j = w - d.
    int dlo = dmin > (w - W_DIM + 1) ? dmin : (w - W_DIM + 1);
    int dhi = (dmax - 1) < w ? (dmax - 1) : w;
    int nvalid = dhi - dlo + 1;
    int jlo, jhi1;
    if (nvalid > 0) { jlo = w - dhi; jhi1 = w - dlo + 1; }
    else           { nvalid = 0; jlo = 0; jhi1 = 0; }

    const float denv = sP[jhi1] - sP[jlo];
    const float qd   = sQ[jhi1] - sQ[jlo];
    const float numv = (float)w * denv - qd;     // sum_d d*e[w-d] over valid d

    // Invalid disparities contribute exp(0)=1 each: closed-form sums.
    float S_valid = (nvalid > 0) ? 0.5f * (float)(dlo + dhi) * (float)nvalid : 0.0f;
    const float S_total = mean_d * (float)D;

    const float den = (float)(D - nvalid) + denv;
    const float num = (S_total - S_valid) + numv;

    out[((cr + C_CH) * H_DIM + h) * W_DIM + w] = num / den;
}

extern "C" void kernel_launch(void* const* d_in, const int* in_sizes, int n_in,
                              void* d_out, int out_size) {
    // metadata order: feaL (unused), feaR, min_disp, max_disp
    const float* feaR = (const float*)d_in[1];
    const int* p_min  = (const int*)d_in[2];
    const int* p_max  = (const int*)d_in[3];
    float* out = (float*)d_out;

    dim3 grid(H_DIM, C_CH);           // 128 x 32 = 4096 blocks, one per right row
    gcnet_scan_kernel<<<grid, W_DIM>>>(feaR, p_min, p_max, out);
}

// round 5
// speedup vs baseline: 2.4335x; 1.3080x over previous
#include <cuda_runtime.h>
#include <cuda_bf16.h>

// B=1, C=32, H=128, W=256. One WARP per right-feature row (cr, h).
// Lane l holds elements [8l, 8l+8) in registers; sequential exclusive
// prefix in registers + one warp shuffle scan of lane totals builds
// E_p[j] = sum_{k<j} exp(x_k), E_q[j] = sum_{k<j} k*exp(x_k) in a
// per-warp private smem region. Each lane then emits 8 outputs at
// w = l + 32*i via O(1) window lookups (conflict-free LDS).

#define C_CH   32
#define H_DIM  128
#define W_DIM  256
#define FULLM  0xFFFFFFFFu
#define WARPS_PER_BLOCK 8
#define EPAD   264            // 257 entries padded to 16B multiple

__global__ __launch_bounds__(256) void gcnet_warprow_kernel(
        const float* __restrict__ feaR,
        const int* __restrict__ p_min,
        const int* __restrict__ p_max,
        float* __restrict__ out) {
    const int lane = threadIdx.x & 31;
    const int wrp  = threadIdx.x >> 5;
    const int row  = blockIdx.x * WARPS_PER_BLOCK + wrp;   // 0..4095
    const int cr   = row >> 7;          // right channel 0..31
    const int h    = row & 127;         // row 0..127

    const int dmin = p_min[0] / 2;
    const int dmax = p_max[0] / 2;
    const int D    = dmax - dmin;
    const float mean_d  = 0.5f * (float)(dmin + dmax - 1);
    const float S_total = mean_d * (float)D;

    __shared__ float sEp[WARPS_PER_BLOCK][EPAD];
    __shared__ float sEq[WARPS_PER_BLOCK][EPAD];
    float* Ep = sEp[wrp];
    float* Eq = sEq[wrp];

    const int rowbase = row * W_DIM;

    // ---- load 8 contiguous elements, exp, local exclusive prefixes ----
    const float4 a = *(const float4*)(feaR + rowbase + 8 * lane);
    const float4 b = *(const float4*)(feaR + rowbase + 8 * lane + 4);

    float p[8];
    p[0] = __expf(a.x); p[1] = __expf(a.y); p[2] = __expf(a.z); p[3] = __expf(a.w);
    p[4] = __expf(b.x); p[5] = __expf(b.y); p[6] = __expf(b.z); p[7] = __expf(b.w);

    const float wbase = (float)(8 * lane);
    float ep[8], eq[8];
    float rp = 0.0f, rq = 0.0f;
    #pragma unroll
    for (int i = 0; i < 8; ++i) {
        ep[i] = rp;  eq[i] = rq;
        rp += p[i];
        rq = fmaf(wbase + (float)i, p[i], rq);
    }
    const float tot_p = rp, tot_q = rq;

    // ---- warp inclusive scan of lane totals ----
    float ip = tot_p, iq = tot_q;
    #pragma unroll
    for (int off = 1; off < 32; off <<= 1) {
        float tp = __shfl_up_sync(FULLM, ip, off);
        float tq = __shfl_up_sync(FULLM, iq, off);
        if (lane >= off) { ip += tp; iq += tq; }
    }
    const float off_p = ip - tot_p;     // exclusive offset for this lane
    const float off_q = iq - tot_q;

    // ---- write exclusive prefix arrays E[0..256] ----
    float4 e0, e1;
    e0.x = ep[0] + off_p; e0.y = ep[1] + off_p; e0.z = ep[2] + off_p; e0.w = ep[3] + off_p;
    e1.x = ep[4] + off_p; e1.y = ep[5] + off_p; e1.z = ep[6] + off_p; e1.w = ep[7] + off_p;
    *(float4*)(Ep + 8 * lane)     = e0;
    *(float4*)(Ep + 8 * lane + 4) = e1;
    e0.x = eq[0] + off_q; e0.y = eq[1] + off_q; e0.z = eq[2] + off_q; e0.w = eq[3] + off_q;
    e1.x = eq[4] + off_q; e1.y = eq[5] + off_q; e1.z = eq[6] + off_q; e1.w = eq[7] + off_q;
    *(float4*)(Eq + 8 * lane)     = e0;
    *(float4*)(Eq + 8 * lane + 4) = e1;
    if (lane == 31) { Ep[W_DIM] = ip; Eq[W_DIM] = iq; }
    __syncwarp();

    // ---- left channel: constant fill (blocked, coalesced 128b stores) ----
    float4 cst = make_float4(mean_d, mean_d, mean_d, mean_d);
    float* outL = out + (cr * H_DIM + h) * W_DIM;
    *(float4*)(outL + 8 * lane)     = cst;
    *(float4*)(outL + 8 * lane + 4) = cst;

    // ---- 8 outputs per lane at w = lane + 32*i (conflict-free lookups) ----
    float* outR = out + ((cr + C_CH) * H_DIM + h) * W_DIM;
    #pragma unroll
    for (int i = 0; i < 8; ++i) {
        const int w   = lane + 32 * i;
        int dlo = dmin > (w - W_DIM + 1) ? dmin : (w - W_DIM + 1);
        int dhi = (dmax - 1) < w ? (dmax - 1) : w;
        int nv  = dhi - dlo + 1;
        float denv = 0.0f, numv = 0.0f, Sv = 0.0f;
        if (nv > 0) {
            const int jlo  = w - dhi;
            const int jhi1 = w - dlo + 1;
            denv = Ep[jhi1] - Ep[jlo];
            const float qd = Eq[jhi1] - Eq[jlo];
            numv = (float)w * denv - qd;
            Sv   = 0.5f * (float)(dlo + dhi) * (float)nv;
        } else {
            nv = 0;
        }
        const float den = (float)(D - nv) + denv;
        const float num = (S_total - Sv) + numv;
        outR[w] = __fdividef(num, den);
    }
}

extern "C" void kernel_launch(void* const* d_in, const int* in_sizes, int n_in,
                              void* d_out, int out_size) {
    // metadata order: feaL (unused), feaR, min_disp, max_disp
    const float* feaR = (const float*)d_in[1];
    const int* p_min  = (const int*)d_in[2];
    const int* p_max  = (const int*)d_in[3];
    float* out = (float*)d_out;

    const int rows = C_CH * H_DIM;                     // 4096 warp-rows
    gcnet_warprow_kernel<<<rows / WARPS_PER_BLOCK, 32 * WARPS_PER_BLOCK>>>(
        feaR, p_min, p_max, out);
}